// round 12
// baseline (speedup 1.0000x reference)
#include <cuda_runtime.h>
#include <cuda_bf16.h>
#include <cstdint>

#define K_CTX 64
#define D     128
#define DS    200

__device__ float g_A[K_CTX * D];                  // raw A = table[t1_ctx]
__device__ __nv_bfloat16 g_AMh[K_CTX * D];        // AM row-major bf16 hi
__device__ __nv_bfloat16 g_AMl[K_CTX * D];        // AM row-major bf16 lo

__device__ __forceinline__ uint32_t smem_to_u32(const void* p) {
    uint32_t a;
    asm("{ .reg .u64 t; cvta.to.shared.u64 t, %1; cvt.u32.u64 %0, t; }"
        : "=r"(a) : "l"(p));
    return a;
}
__device__ __forceinline__ void ldm_x4(uint32_t* r, uint32_t addr) {
    asm volatile("ldmatrix.sync.aligned.m8n8.x4.shared.b16 {%0,%1,%2,%3}, [%4];"
        : "=r"(r[0]), "=r"(r[1]), "=r"(r[2]), "=r"(r[3]) : "r"(addr));
}
__device__ __forceinline__ void mma_bf16(float* d, const uint32_t* a,
                                         uint32_t b0, uint32_t b1) {
    asm volatile(
        "mma.sync.aligned.m16n8k16.row.col.f32.bf16.bf16.f32 "
        "{%0,%1,%2,%3}, {%4,%5,%6,%7}, {%8,%9}, {%0,%1,%2,%3};"
        : "+f"(d[0]), "+f"(d[1]), "+f"(d[2]), "+f"(d[3])
        : "r"(a[0]), "r"(a[1]), "r"(a[2]), "r"(a[3]), "r"(b0), "r"(b1));
}
__device__ __forceinline__ float tanh_fast(float x) {
    x = fminf(fmaxf(x, -15.f), 15.f);
    float e = __expf(2.f * x);
    return __fdividef(e - 1.f, e + 1.f);
}

// ---- prep: AM = table[t1_ctx] @ att -> bf16 hi/lo row-major; also g_A ----
__global__ __launch_bounds__(1024)
void prep_kernel(const float* __restrict__ table,
                 const float* __restrict__ att,
                 const int* __restrict__ t1_ctx) {
    __shared__ float partial[8 * D];
    const int k = blockIdx.x;
    const int t = threadIdx.x;
    const int j = t & 127;
    const int s = t >> 7;
    const int d0 = s * 16;

    const size_t idx = (size_t)t1_ctx[k];
    float4 a4[4];
    const float4* arow = (const float4*)(table + idx * D);
#pragma unroll
    for (int i = 0; i < 4; ++i) a4[i] = arow[s * 4 + i];
    float w[16];
#pragma unroll
    for (int i = 0; i < 16; ++i) w[i] = att[(d0 + i) * D + j];

    const float* a = (const float*)a4;
    float s0 = 0.f, s1 = 0.f, s2 = 0.f, s3 = 0.f;
#pragma unroll
    for (int i = 0; i < 16; i += 4) {
        s0 = fmaf(a[i + 0], w[i + 0], s0);
        s1 = fmaf(a[i + 1], w[i + 1], s1);
        s2 = fmaf(a[i + 2], w[i + 2], s2);
        s3 = fmaf(a[i + 3], w[i + 3], s3);
    }
    partial[s * D + j] = (s0 + s1) + (s2 + s3);
    __syncthreads();

    if (s == 0) {
        float r = 0.f;
#pragma unroll
        for (int p = 0; p < 8; ++p) r += partial[p * D + j];
        __nv_bfloat16 hi = __float2bfloat16(r);
        __nv_bfloat16 lo = __float2bfloat16(r - __bfloat162float(hi));
        g_AMh[k * D + j] = hi;
        g_AMl[k * D + j] = lo;
        g_A[k * D + j] = table[idx * D + j];
    }
}

// ---- fused: mma.sync GEMM + in-register means + softmax + bilinear + cosine ----
#define BSTRIDE 68   // words per bf16 image row (272B, ldmatrix conflict-free)
#define FSTRIDE 132  // words per f32 B row
static constexpr int W_AMH  = 0;                       // 64*68
static constexpr int W_AML  = W_AMH + 64 * BSTRIDE;
static constexpr int W_BH   = W_AML + 64 * BSTRIDE;
static constexpr int W_BL   = W_BH  + 64 * BSTRIDE;
static constexpr int W_BF   = W_BL  + 64 * BSTRIDE;    // 64*132 f32 B
static constexpr int W_ROWP = W_BF + 64 * FSTRIDE;     // 2*64
static constexpr int W_COLP = W_ROWP + 128;            // 4*64
static constexpr int W_RW   = W_COLP + 256;            // 64
static constexpr int W_CW   = W_RW + 64;               // 64
static constexpr int W_NA   = W_CW + 64;               // 128
static constexpr int W_NB   = W_NA + 128;              // 128
static constexpr int W_RED  = W_NB + 128;              // 256
static constexpr int W_PART = W_RED + 256;             // 32
static constexpr int SMEM_WORDS = W_PART + 32;
static constexpr int FUSED_SMEM = SMEM_WORDS * 4;

__global__ __launch_bounds__(256, 2)
void fused_kernel(const float* __restrict__ table,
                  const float* __restrict__ str_t1,
                  const float* __restrict__ str_t2s,
                  const float* __restrict__ W,
                  const float* __restrict__ b_bi,
                  const int* __restrict__ t2_ctx,
                  float* __restrict__ out) {
    extern __shared__ uint32_t smw[];
    float* smf = (float*)smw;

    const int t    = threadIdx.x;
    const int c    = blockIdx.x;
    const int lane = t & 31;
    const int w    = t >> 5;      // 8 warps
    const int wr   = w & 3;       // k-tile: rows 16wr..16wr+15
    const int wc   = w >> 2;      // m-half: cols 32wc..32wc+31
    const uint32_t sbase = smem_to_u32(smw);

    float x1 = 0.f, x2 = 0.f;
    if (t < DS) { x1 = str_t1[t]; x2 = str_t2s[c * DS + t]; }

    // stage AM bf16 hi/lo images
    {
        const uint4* sh = (const uint4*)g_AMh;
        const uint4* sl = (const uint4*)g_AMl;
        uint4* dh = (uint4*)(smw + W_AMH);
        uint4* dl = (uint4*)(smw + W_AML);
#pragma unroll
        for (int i = 0; i < 4; ++i) {
            int idx = t + 256 * i;
            int r = idx >> 4, cc = idx & 15;
            dh[r * 17 + cc] = sh[idx];
            dl[r * 17 + cc] = sl[idx];
        }
    }

    // gather 64 B rows: keep f32 copy + bf16 hi/lo images
    {
        const int r = t >> 2, l = t & 3;
        size_t idx = (size_t)t2_ctx[c * K_CTX + r];
        const float4* src = (const float4*)(table + idx * D);
        uint32_t* bh = smw + W_BH + r * BSTRIDE + l * 16;
        uint32_t* bl = smw + W_BL + r * BSTRIDE + l * 16;
        float4* bf = (float4*)(smw + W_BF + r * FSTRIDE);
#pragma unroll
        for (int i = 0; i < 8; ++i) {
            float4 f = src[l * 8 + i];
            bf[l * 8 + i] = f;
            __nv_bfloat162 h01 = __floats2bfloat162_rn(f.x, f.y);
            __nv_bfloat162 h23 = __floats2bfloat162_rn(f.z, f.w);
            __nv_bfloat162 l01 = __floats2bfloat162_rn(
                f.x - __bfloat162float(h01.x), f.y - __bfloat162float(h01.y));
            __nv_bfloat162 l23 = __floats2bfloat162_rn(
                f.z - __bfloat162float(h23.x), f.w - __bfloat162float(h23.y));
            *(uint2*)(bh + 2 * i) = make_uint2(*(uint32_t*)&h01, *(uint32_t*)&h23);
            *(uint2*)(bl + 2 * i) = make_uint2(*(uint32_t*)&l01, *(uint32_t*)&l23);
        }
    }
    __syncthreads();

    // ---- S(64x64) = AM @ B^T via m16n8k16 bf16, 3-term hi/lo ----
    float acc[4][4];
#pragma unroll
    for (int i = 0; i < 4; ++i)
#pragma unroll
        for (int j = 0; j < 4; ++j) acc[i][j] = 0.f;

    {
        const uint32_t aoff = (uint32_t)((16 * wr + (lane & 15)) * 272 +
                                         (lane >> 4) * 16);
        const uint32_t aH = sbase + W_AMH * 4 + aoff;
        const uint32_t aL = sbase + W_AML * 4 + aoff;
        const int bn = (lane & 7) + ((lane >> 4) << 3);
        const uint32_t brow = ((lane >> 3) & 1) * 16;

#pragma unroll
        for (int kk = 0; kk < 8; ++kk) {
            uint32_t ah[4], al[4];
            ldm_x4(ah, aH + kk * 32);
            ldm_x4(al, aL + kk * 32);
#pragma unroll
            for (int np = 0; np < 2; ++np) {
                const int n0 = 32 * wc + 16 * np;
                const uint32_t bo = (uint32_t)((n0 + bn) * 272 + kk * 32 + brow);
                uint32_t bh4[4], bl4[4];
                ldm_x4(bh4, sbase + W_BH * 4 + bo);
                ldm_x4(bl4, sbase + W_BL * 4 + bo);
                mma_bf16(acc[2 * np + 0], ah, bh4[0], bh4[1]);
                mma_bf16(acc[2 * np + 0], al, bh4[0], bh4[1]);
                mma_bf16(acc[2 * np + 0], ah, bl4[0], bl4[1]);
                mma_bf16(acc[2 * np + 1], ah, bh4[2], bh4[3]);
                mma_bf16(acc[2 * np + 1], al, bh4[2], bh4[3]);
                mma_bf16(acc[2 * np + 1], ah, bl4[2], bl4[3]);
            }
        }
    }

    // tanh in-register; S never materialized
#pragma unroll
    for (int i = 0; i < 4; ++i)
#pragma unroll
        for (int j = 0; j < 4; ++j) acc[i][j] = tanh_fast(acc[i][j]);

    // row sums (per k, over m): in-reg over nt/cols, shfl over lane bits 0-1
    {
        float rs0 = 0.f, rs1 = 0.f;
#pragma unroll
        for (int nt = 0; nt < 4; ++nt) {
            rs0 += acc[nt][0] + acc[nt][1];   // row kr
            rs1 += acc[nt][2] + acc[nt][3];   // row kr+8
        }
        rs0 += __shfl_xor_sync(0xffffffffu, rs0, 1);
        rs0 += __shfl_xor_sync(0xffffffffu, rs0, 2);
        rs1 += __shfl_xor_sync(0xffffffffu, rs1, 1);
        rs1 += __shfl_xor_sync(0xffffffffu, rs1, 2);
        if ((lane & 3) == 0) {
            const int kr = 16 * wr + (lane >> 2);
            smf[W_ROWP + wc * 64 + kr]     = rs0;
            smf[W_ROWP + wc * 64 + kr + 8] = rs1;
        }
    }
    // col sums (per m, over k): in-reg over rows, shfl over lane bits 2-4
    {
        float cs[4][2];
#pragma unroll
        for (int nt = 0; nt < 4; ++nt) {
            cs[nt][0] = acc[nt][0] + acc[nt][2];
            cs[nt][1] = acc[nt][1] + acc[nt][3];
#pragma unroll
            for (int o = 4; o <= 16; o <<= 1) {
                cs[nt][0] += __shfl_xor_sync(0xffffffffu, cs[nt][0], o);
                cs[nt][1] += __shfl_xor_sync(0xffffffffu, cs[nt][1], o);
            }
        }
        if (lane < 4) {
#pragma unroll
            for (int nt = 0; nt < 4; ++nt) {
                const int m = 32 * wc + 8 * nt + 2 * lane;
                smf[W_COLP + wr * 64 + m]     = cs[nt][0];
                smf[W_COLP + wr * 64 + m + 1] = cs[nt][1];
            }
        }
    }
    __syncthreads();

    // combine partials into means
    if (t < 64) {
        smf[W_RW + t] = (smf[W_ROWP + t] + smf[W_ROWP + 64 + t]) * (1.f / 64.f);
    } else if (t < 128) {
        const int m = t - 64;
        smf[W_CW + m] = (smf[W_COLP + m] + smf[W_COLP + 64 + m] +
                         smf[W_COLP + 128 + m] + smf[W_COLP + 192 + m]) * (1.f / 64.f);
    }
    __syncthreads();

    // dual softmax: warp0 -> rows, warp1 -> cols
    if (t < 64) {
        float* vec = smf + ((t < 32) ? W_RW : W_CW);
        float v0 = vec[lane], v1 = vec[lane + 32];
        float mx = fmaxf(v0, v1);
#pragma unroll
        for (int o = 16; o >= 1; o >>= 1)
            mx = fmaxf(mx, __shfl_xor_sync(0xffffffffu, mx, o));
        float e0 = __expf(v0 - mx), e1 = __expf(v1 - mx);
        float s = e0 + e1;
#pragma unroll
        for (int o = 16; o >= 1; o >>= 1)
            s += __shfl_xor_sync(0xffffffffu, s, o);
        float inv = __fdividef(1.f, s);
        vec[lane] = e0 * inv;
        vec[lane + 32] = e1 * inv;
    }
    __syncthreads();

    // nA from g_A (L2-hot coalesced); nB from f32 B in smem
    if (t < 128) {
        float s0 = 0.f, s1 = 0.f, s2 = 0.f, s3 = 0.f;
        const float* rw = smf + W_RW;
#pragma unroll
        for (int k = 0; k < K_CTX; k += 4) {
            s0 = fmaf(rw[k + 0], g_A[(k + 0) * D + t], s0);
            s1 = fmaf(rw[k + 1], g_A[(k + 1) * D + t], s1);
            s2 = fmaf(rw[k + 2], g_A[(k + 2) * D + t], s2);
            s3 = fmaf(rw[k + 3], g_A[(k + 3) * D + t], s3);
        }
        smf[W_NA + t] = (s0 + s1) + (s2 + s3);
    } else {
        const int dd = t - 128;
        const float* cw = smf + W_CW;
        const float* b = smf + W_BF + dd;
        float s0 = 0.f, s1 = 0.f, s2 = 0.f, s3 = 0.f;
#pragma unroll
        for (int m = 0; m < K_CTX; m += 4) {
            s0 = fmaf(cw[m + 0], b[(m + 0) * FSTRIDE], s0);
            s1 = fmaf(cw[m + 1], b[(m + 1) * FSTRIDE], s1);
            s2 = fmaf(cw[m + 2], b[(m + 2) * FSTRIDE], s2);
            s3 = fmaf(cw[m + 3], b[(m + 3) * FSTRIDE], s3);
        }
        smf[W_NB + dd] = (s0 + s1) + (s2 + s3);
    }
    __syncthreads();

    // bilinear: split d across the two thread halves
    {
        const int col = t & 127, half = t >> 7;
        const int d0 = half * 64;
        float s = 0.f;
        const float* nA = smf + W_NA;
#pragma unroll 4
        for (int d = d0; d < d0 + 64; ++d)
            s = fmaf(nA[d], W[d * D + col], s);
        smf[W_RED + t] = s;
    }
    __syncthreads();
    if (t < 128) {
        float v = (smf[W_RED + t] + smf[W_RED + t + 128]) * smf[W_NB + t];
#pragma unroll
        for (int o = 16; o >= 1; o >>= 1)
            v += __shfl_xor_sync(0xffffffffu, v, o);
        if (lane == 0) smf[W_PART + w] = v;
    }

    // string cosine partials (8 warps)
    {
        float p11 = x1 * x1, p22 = x2 * x2, p12 = x1 * x2;
#pragma unroll
        for (int o = 16; o >= 1; o >>= 1) {
            p11 += __shfl_xor_sync(0xffffffffu, p11, o);
            p22 += __shfl_xor_sync(0xffffffffu, p22, o);
            p12 += __shfl_xor_sync(0xffffffffu, p12, o);
        }
        if (lane == 0) {
            smf[W_PART + 8 + w]  = p11;
            smf[W_PART + 16 + w] = p22;
            smf[W_PART + 24 + w] = p12;
        }
    }
    __syncthreads();

    if (t == 0) {
        float con = smf[W_PART + 0] + smf[W_PART + 1] +
                    smf[W_PART + 2] + smf[W_PART + 3] + b_bi[0];
        float s11 = 0.f, s22 = 0.f, s12 = 0.f;
#pragma unroll
        for (int i = 0; i < 8; ++i) {
            s11 += smf[W_PART + 8 + i];
            s22 += smf[W_PART + 16 + i];
            s12 += smf[W_PART + 24 + i];
        }
        float n1 = fmaxf(sqrtf(s11), 1e-8f);
        float n2 = fmaxf(sqrtf(s22), 1e-8f);
        out[c] = 0.5f * (s12 / (n1 * n2)) + 0.5f * con;
    }
}

extern "C" void kernel_launch(void* const* d_in, const int* in_sizes, int n_in,
                              void* d_out, int out_size) {
    const float* table   = (const float*)d_in[0];
    const float* str_t1  = (const float*)d_in[1];
    const float* str_t2s = (const float*)d_in[2];
    const float* att_mat = (const float*)d_in[3];
    const float* W_bi    = (const float*)d_in[4];
    const float* b_bi    = (const float*)d_in[5];
    const int*   t1_ctx  = (const int*)d_in[6];
    const int*   t2_ctx  = (const int*)d_in[7];
    float* out = (float*)d_out;

    cudaFuncSetAttribute(fused_kernel,
                         cudaFuncAttributeMaxDynamicSharedMemorySize, FUSED_SMEM);

    prep_kernel<<<K_CTX, 1024>>>(table, att_mat, t1_ctx);
    fused_kernel<<<256, 256, FUSED_SMEM>>>(table, str_t1, str_t2s, W_bi, b_bi,
                                           t2_ctx, out);
}